// round 9
// baseline (speedup 1.0000x reference)
#include <cuda_runtime.h>
#include <math.h>

#define BATCH 128
#define NDIM 512
#define POWER_ITERS 10
#define N_ITERS 500
#define NTHREADS 512
#define NWARPS 16
#define NTILES 136              // 16*17/2 upper-triangular 32x32 tiles
#define TILE_ELEMS 1024
#define INST_STRIDE (NTILES * TILE_ELEMS)   // 544 KB per instance

// Packed symmetric Sigma: 128 * 544KB = 68 MB (L2-resident)
__device__ float g_pack[(size_t)BATCH * INST_STRIDE];

// ---------------------------------------------------------------------------
// Kernel 1: symmetrize + pack upper triangle. T = 0.5(S_IJ + S_JI^T).
//  diag tile (I==J):  P[k*128 + c*4 + j] = T[4k+j][c]        (col layout)
//  off-diag (I<J):    P[k*128 + i*4 + j] = T[(i+4k+j)&31][i] (diag-shifted)
// Both give float4-per-lane LDG in the solver.
// ---------------------------------------------------------------------------
__global__ void pack_kernel(const float* __restrict__ Sigma) {
    __shared__ float sA[32][33];
    __shared__ float sB[32][33];
    const int t = blockIdx.x;
    const int b = blockIdx.y;
    int I = 0, rem = t;
    while (rem >= 16 - I) { rem -= 16 - I; ++I; }
    const int J = I + rem;

    const float* S = Sigma + (size_t)b * NDIM * NDIM;
    float* P = g_pack + (size_t)b * INST_STRIDE + (size_t)t * TILE_ELEMS;
    const int tx = threadIdx.x, ty = threadIdx.y;
    const int tid = ty * 32 + tx;

    #pragma unroll
    for (int r = ty; r < 32; r += 8) {
        sA[r][tx] = S[(size_t)(I * 32 + r) * NDIM + J * 32 + tx]; // S[Ib+r][Jb+c]
        sB[r][tx] = S[(size_t)(J * 32 + r) * NDIM + I * 32 + tx]; // S[Jb+r][Ib+c]
    }
    __syncthreads();

    const bool diag = (I == J);
    #pragma unroll
    for (int q = 0; q < 4; ++q) {
        const int addr = tid + (q << 8);
        const int k = addr >> 7;
        const int c = (addr >> 2) & 31;
        const int j = addr & 3;
        const int r = diag ? ((k << 2) + j) : ((c + (k << 2) + j) & 31);
        P[addr] = 0.5f * (sA[r][c] + sB[c][r]);   // T[r][c]
    }
}

// ---------------------------------------------------------------------------
// reductions
// ---------------------------------------------------------------------------
__device__ __forceinline__ float warp_sum(float v) {
    #pragma unroll
    for (int o = 16; o; o >>= 1) v += __shfl_xor_sync(0xffffffffu, v, o);
    return v;
}
__device__ __forceinline__ float warp_max(float v) {
    #pragma unroll
    for (int o = 16; o; o >>= 1) v = fmaxf(v, __shfl_xor_sync(0xffffffffu, v, o));
    return v;
}
__device__ __forceinline__ float block_sum(float v, volatile float* red,
                                           int lane, int wid) {
    v = warp_sum(v);
    __syncthreads();
    if (lane == 0) red[wid] = v;
    __syncthreads();
    float x = (lane < NWARPS) ? red[lane] : 0.0f;
    return warp_sum(x);
}

// ---------------------------------------------------------------------------
// Symmetric matvec. Off-diag tiles: col product via rotated LDS, row product
// via SHFL (no SMEM staging). Diag tiles: broadcast col product.
// Returns (Ssym*y)[tid].
// ---------------------------------------------------------------------------
__device__ __forceinline__ float matvec_sym(const float* __restrict__ P,
                                            const float* __restrict__ sy,
                                            float* __restrict__ accAll,
                                            const int* __restrict__ tI,
                                            const int* __restrict__ tJ,
                                            int tid, int lane, int wid) {
    float* acc = accAll + (wid << 9);
    {
        const float4 z = make_float4(0.f, 0.f, 0.f, 0.f);
        float4* a4 = (float4*)acc;
        a4[lane] = z; a4[lane + 32] = z; a4[lane + 64] = z; a4[lane + 96] = z;
    }

    for (int t = wid; t < NTILES; t += NWARPS) {
        const float4* PT4 = (const float4*)(P + t * TILE_ELEMS);
        const int I = tI[t], J = tJ[t];
        if (I == J) {
            const float4* yb4 = (const float4*)(sy + (I << 5));
            float a0 = 0.f, a1 = 0.f;
            #pragma unroll
            for (int k = 0; k < 8; ++k) {
                const float4 e  = PT4[(k << 5) + lane];
                const float4 yb = yb4[k];                 // broadcast
                a0 = fmaf(e.x, yb.x, a0); a1 = fmaf(e.y, yb.y, a1);
                a0 = fmaf(e.z, yb.z, a0); a1 = fmaf(e.w, yb.w, a1);
            }
            acc[(I << 5) + lane] += a0 + a1;
        } else {
            const float* yI  = sy + (I << 5);
            const float  ryJ = sy[(J << 5) + lane];       // coalesced
            float c0 = 0.f, c1 = 0.f, c2 = 0.f, c3 = 0.f;
            float r0 = 0.f, r1 = 0.f, r2 = 0.f, r3 = 0.f;
            #pragma unroll
            for (int k = 0; k < 8; ++k) {
                const float4 e = PT4[(k << 5) + lane];    // d = 4k+j at lane i
                const int d0 = k << 2;
                const int b0 = lane + d0;
                // column product: e_j pairs with yI[(i+d)&31]  (perm LDS)
                c0 = fmaf(e.x, yI[(b0 + 0) & 31], c0);
                c1 = fmaf(e.y, yI[(b0 + 1) & 31], c1);
                c2 = fmaf(e.z, yI[(b0 + 2) & 31], c2);
                c3 = fmaf(e.w, yI[(b0 + 3) & 31], c3);
                // row product: lane r receives T[r][c]*yJ[c] from c=(r-d)&31
                const float t0 = e.x * ryJ, t1 = e.y * ryJ;
                const float t2 = e.z * ryJ, t3 = e.w * ryJ;
                r0 += __shfl_sync(0xffffffffu, t0, (lane - d0    ) & 31);
                r1 += __shfl_sync(0xffffffffu, t1, (lane - d0 - 1) & 31);
                r2 += __shfl_sync(0xffffffffu, t2, (lane - d0 - 2) & 31);
                r3 += __shfl_sync(0xffffffffu, t3, (lane - d0 - 3) & 31);
            }
            acc[(J << 5) + lane] += (c0 + c1) + (c2 + c3);
            acc[(I << 5) + lane] += (r0 + r1) + (r2 + r3);
        }
    }
    __syncthreads();
    float s0 = 0.f, s1 = 0.f, s2 = 0.f, s3 = 0.f;
    #pragma unroll
    for (int w = 0; w < 4; ++w) {
        s0 += accAll[((4 * w + 0) << 9) + tid];
        s1 += accAll[((4 * w + 1) << 9) + tid];
        s2 += accAll[((4 * w + 2) << 9) + tid];
        s3 += accAll[((4 * w + 3) << 9) + tid];
    }
    return (s0 + s1) + (s2 + s3);
}

// prefetch one 4KB tile into L1: each lane touches one 128B line
__device__ __forceinline__ void prefetch_tile(const float* __restrict__ P,
                                              int t, int lane) {
    const char* p = (const char*)(P + t * TILE_ELEMS) + (lane << 7);
    asm volatile("prefetch.global.L1 [%0];" :: "l"(p));
}

// ---------------------------------------------------------------------------
// Kernel 2: per-instance solver. grid=128 CTAs, block=512 threads.
// ---------------------------------------------------------------------------
__global__ void __launch_bounds__(NTHREADS, 1)
qp_solver_kernel(const float* __restrict__ mu_g, float* __restrict__ out) {
    __shared__ float accAll[NWARPS * NDIM];   // 32 KB
    __shared__ float sy[NDIM];
    __shared__ float sv[NDIM];
    __shared__ float sw[NDIM];
    __shared__ float red[NWARPS];
    __shared__ int   sh_tI[NTILES], sh_tJ[NTILES];
    __shared__ int   sflag;

    const int b    = blockIdx.x;
    const int tid  = threadIdx.x;
    const int lane = tid & 31;
    const int wid  = tid >> 5;
    const float* P = g_pack + (size_t)b * INST_STRIDE;
    const float invN = 1.0f / (float)NDIM;

    if (tid < NTILES) {
        int I = 0, rem = tid;
        while (rem >= 16 - I) { rem -= 16 - I; ++I; }
        sh_tI[tid] = I;
        sh_tJ[tid] = I + rem;
    }
    if (tid == 0) sflag = 0;
    const float rmu = mu_g[(size_t)b * NDIM + tid];
    sy[tid] = invN;
    __syncthreads();

    // ---- power iteration (answer is step-independent; margin below) ----
    float ry = invN;
    for (int it = 0; it < POWER_ITERS; ++it) {
        const float gi = matvec_sym(P, sy, accAll, sh_tI, sh_tJ, tid, lane, wid);
        const float ss = block_sum(gi * gi, red, lane, wid);
        const float inv = 1.0f / (sqrtf(ss) + 1e-12f);
        ry = gi * inv;
        sy[tid] = ry;                         // safe: block_sum barriers passed
        __syncthreads();
    }
    const float gi0  = matvec_sym(P, sy, accAll, sh_tI, sh_tJ, tid, lane, wid);
    const float lmax = block_sum(ry * gi0, red, lane, wid);
    const float step = 1.0f / (2.0f * lmax * 1.08f + 1e-8f);  // 8% margin

    // ---- FISTA with adaptive restart; scalar phase on warp 0 ----
    sy[tid] = invN;
    sw[tid] = invN;
    __syncthreads();
    float t_mom = 1.0f;                       // meaningful in warp 0 only

    for (int it = 0; it < N_ITERS; ++it) {
        const float gi = matvec_sym(P, sy, accAll, sh_tI, sh_tJ, tid, lane, wid);
        sv[tid] = sy[tid] - step * (2.0f * gi - rmu);
        prefetch_tile(P, wid, lane);          // warm L1 for next matvec
        __syncthreads();                      // (B) sv ready

        if (wid == 0) {
            float vv[16];
            #pragma unroll
            for (int j = 0; j < 16; ++j) vv[j] = sv[(j << 5) + lane];

            // simplex projection: Michelot fixed point (== sort-based theta)
            float s = 0.f;
            #pragma unroll
            for (int j = 0; j < 16; ++j) s += vv[j];
            s = warp_sum(s);
            float theta = (s - 1.0f) * invN;
            #pragma unroll 1
            for (int pit = 0; pit < 40; ++pit) {
                float sa = 0.f, sc = 0.f;
                #pragma unroll
                for (int j = 0; j < 16; ++j) {
                    if (vv[j] > theta) { sa += vv[j]; sc += 1.0f; }
                }
                sa = warp_sum(sa); sc = warp_sum(sc);
                const float tn = (sa - 1.0f) / sc;
                if (tn == theta) break;       // uniform across warp
                theta = tn;
            }

            // restart test + convergence check
            float mx = 0.f, rdot = 0.f;
            #pragma unroll
            for (int j = 0; j < 16; ++j) {
                const float wo  = sw[(j << 5) + lane];
                const float yo  = sy[(j << 5) + lane];
                const float wnj = fmaxf(vv[j] - theta, 0.0f);
                mx   = fmaxf(mx, fabsf(wnj - wo));
                rdot += (yo - wnj) * (wnj - wo);
            }
            mx = warp_max(mx); rdot = warp_sum(rdot);

            float coef;
            if (rdot > 0.0f) { t_mom = 1.0f; coef = 0.0f; }
            else {
                const float tn = 0.5f * (1.0f + sqrtf(1.0f + 4.0f * t_mom * t_mom));
                coef = (t_mom - 1.0f) / tn;
                t_mom = tn;
            }
            #pragma unroll
            for (int j = 0; j < 16; ++j) {
                const float wo  = sw[(j << 5) + lane];
                const float wnj = fmaxf(vv[j] - theta, 0.0f);
                sw[(j << 5) + lane] = wnj;
                sy[(j << 5) + lane] = wnj + coef * (wnj - wo);
            }
            if (lane == 0) sflag = (mx < 1e-6f) ? 1 : 0;
        }
        __syncthreads();                      // (C) sy/sw/sflag ready
        if (sflag) break;                     // uniform
    }

    out[(size_t)b * NDIM + tid] = sw[tid];
}

// ---------------------------------------------------------------------------
extern "C" void kernel_launch(void* const* d_in, const int* in_sizes, int n_in,
                              void* d_out, int out_size) {
    const float* mu    = (const float*)d_in[0];   // [128, 512]
    const float* Sigma = (const float*)d_in[1];   // [128, 512, 512]
    float* out = (float*)d_out;                   // [128, 512]

    dim3 gs(NTILES, BATCH);
    dim3 bs(32, 8);
    pack_kernel<<<gs, bs>>>(Sigma);
    qp_solver_kernel<<<BATCH, NTHREADS>>>(mu, out);
}

// round 10
// speedup vs baseline: 1.4038x; 1.4038x over previous
#include <cuda_runtime.h>
#include <math.h>

#define BATCH 128
#define NDIM 512
#define POWER_ITERS 10
#define N_ITERS 500
#define NTHREADS 512
#define NWARPS 16
#define NTILES 136              // 16*17/2 upper-triangular 32x32 tiles
#define TILE_ELEMS 1024
#define INST_STRIDE (NTILES * TILE_ELEMS)   // 544 KB per instance

// dynamic smem layout (floats)
#define ACC_OFF   0                          // 16 x 512  (32 KB)
#define STAGE_OFF 8192                       // 16 x 1152 (72 KB)
#define SY_OFF    (STAGE_OFF + 16 * 1152)
#define SV_OFF    (SY_OFF + NDIM)
#define SW_OFF    (SV_OFF + NDIM)
#define DSM_FLOATS (SW_OFF + NDIM)
#define DSM_BYTES (DSM_FLOATS * 4)           // 112,640 B

// Packed symmetric Sigma: 128 * 544KB = 68 MB (L2-resident)
__device__ float g_pack[(size_t)BATCH * INST_STRIDE];

// ---------------------------------------------------------------------------
// Kernel 1: symmetrize + pack upper triangle (uniform column layout).
// P[k*128 + c*4 + j] = T[4k+j][c],  T = 0.5(S_IJ + S_JI^T)
// ---------------------------------------------------------------------------
__global__ void pack_kernel(const float* __restrict__ Sigma) {
    __shared__ float sA[32][33];
    __shared__ float sB[32][33];
    const int t = blockIdx.x;
    const int b = blockIdx.y;
    int I = 0, rem = t;
    while (rem >= 16 - I) { rem -= 16 - I; ++I; }
    const int J = I + rem;

    const float* S = Sigma + (size_t)b * NDIM * NDIM;
    float* P = g_pack + (size_t)b * INST_STRIDE + (size_t)t * TILE_ELEMS;
    const int tx = threadIdx.x, ty = threadIdx.y;
    const int tid = ty * 32 + tx;

    #pragma unroll
    for (int r = ty; r < 32; r += 8) {
        sA[r][tx] = S[(size_t)(I * 32 + r) * NDIM + J * 32 + tx]; // S[Ib+r][Jb+c]
        sB[r][tx] = S[(size_t)(J * 32 + r) * NDIM + I * 32 + tx]; // S[Jb+r][Ib+c]
    }
    __syncthreads();

    #pragma unroll
    for (int q = 0; q < 4; ++q) {
        const int addr = tid + (q << 8);
        const int k = addr >> 7;
        const int c = (addr >> 2) & 31;
        const int j = addr & 3;
        const int r = (k << 2) + j;
        P[addr] = 0.5f * (sA[r][c] + sB[c][r]);   // T[r][c]
    }
}

// ---------------------------------------------------------------------------
// reductions
// ---------------------------------------------------------------------------
__device__ __forceinline__ float warp_sum(float v) {
    #pragma unroll
    for (int o = 16; o; o >>= 1) v += __shfl_xor_sync(0xffffffffu, v, o);
    return v;
}
__device__ __forceinline__ float warp_max(float v) {
    #pragma unroll
    for (int o = 16; o; o >>= 1) v = fmaxf(v, __shfl_xor_sync(0xffffffffu, v, o));
    return v;
}
__device__ __forceinline__ float block_sum(float v, volatile float* red,
                                           int lane, int wid) {
    v = warp_sum(v);
    __syncthreads();
    if (lane == 0) red[wid] = v;
    __syncthreads();
    float x = (lane < NWARPS) ? red[lane] : 0.0f;
    return warp_sum(x);
}

// prefetch one 4KB tile into L1: each lane touches one 128B line
__device__ __forceinline__ void prefetch_tile(const float* __restrict__ P,
                                              int t, int lane) {
    const char* p = (const char*)(P + t * TILE_ELEMS) + (lane << 7);
    asm volatile("prefetch.global.L1 [%0];" :: "l"(p));
}

// ---------------------------------------------------------------------------
// Symmetric matvec, staged two-pass per tile, balanced static schedule.
// sched entry: (tileIdx<<8)|(I<<4)|J, -1 = empty. Returns (Ssym*y)[tid].
// ---------------------------------------------------------------------------
__device__ __forceinline__ float matvec_sym(const float* __restrict__ P,
                                            const float* __restrict__ sy,
                                            float* __restrict__ accAll,
                                            float* __restrict__ stageAll,
                                            const int* __restrict__ sched,
                                            int tid, int lane, int wid) {
    float* acc = accAll + (wid << 9);
    {
        const float4 z = make_float4(0.f, 0.f, 0.f, 0.f);
        float4* a4 = (float4*)acc;
        a4[lane] = z; a4[lane + 32] = z; a4[lane + 64] = z; a4[lane + 96] = z;
    }
    float* stg = stageAll + wid * 1152;
    const int* ms = sched + wid * 10;

    #pragma unroll 1
    for (int m = 0; m < 9; ++m) {
        const int e = ms[m];
        if (e < 0) break;                      // only trailing sentinels
        const int en = ms[m + 1];
        if (en >= 0) prefetch_tile(P, en >> 8, lane);   // hide L2 latency

        const int t = e >> 8;
        const int I = (e >> 4) & 15, J = e & 15;
        const float4* PT4 = (const float4*)(P + t * TILE_ELEMS);
        const float4* yI4 = (const float4*)(sy + (I << 5));
        float a0 = 0.f, a1 = 0.f;
        if (I == J) {
            #pragma unroll
            for (int k = 0; k < 8; ++k) {
                const float4 e4 = PT4[(k << 5) + lane];
                const float4 yb = yI4[k];                 // broadcast
                a0 = fmaf(e4.x, yb.x, a0); a1 = fmaf(e4.y, yb.y, a1);
                a0 = fmaf(e4.z, yb.z, a0); a1 = fmaf(e4.w, yb.w, a1);
            }
            acc[(I << 5) + lane] += a0 + a1;
        } else {
            #pragma unroll
            for (int k = 0; k < 8; ++k) {
                const float4 e4 = PT4[(k << 5) + lane];   // rows 4k..4k+3, col=lane
                const float4 yb = yI4[k];
                a0 = fmaf(e4.x, yb.x, a0); a1 = fmaf(e4.y, yb.y, a1);
                a0 = fmaf(e4.z, yb.z, a0); a1 = fmaf(e4.w, yb.w, a1);
                stg[((k << 2) + 0) * 36 + lane] = e4.x;   // conflict-free
                stg[((k << 2) + 1) * 36 + lane] = e4.y;
                stg[((k << 2) + 2) * 36 + lane] = e4.z;
                stg[((k << 2) + 3) * 36 + lane] = e4.w;
            }
            acc[(J << 5) + lane] += a0 + a1;              // (T^T yI) -> block J
            __syncwarp();
            const float4* yJ4 = (const float4*)(sy + (J << 5));
            float b0 = 0.f, b1 = 0.f;
            #pragma unroll
            for (int mm = 0; mm < 8; ++mm) {
                const float4 s  = *(const float4*)(stg + lane * 36 + (mm << 2));
                const float4 yb = yJ4[mm];
                b0 = fmaf(s.x, yb.x, b0); b1 = fmaf(s.y, yb.y, b1);
                b0 = fmaf(s.z, yb.z, b0); b1 = fmaf(s.w, yb.w, b1);
            }
            acc[(I << 5) + lane] += b0 + b1;              // (T yJ) -> block I
            __syncwarp();
        }
    }
    __syncthreads();
    float s0 = 0.f, s1 = 0.f, s2 = 0.f, s3 = 0.f;
    #pragma unroll
    for (int w = 0; w < 4; ++w) {
        s0 += accAll[((4 * w + 0) << 9) + tid];
        s1 += accAll[((4 * w + 1) << 9) + tid];
        s2 += accAll[((4 * w + 2) << 9) + tid];
        s3 += accAll[((4 * w + 3) << 9) + tid];
    }
    return (s0 + s1) + (s2 + s3);
}

// ---------------------------------------------------------------------------
// Kernel 2: per-instance solver. grid=128 CTAs, block=512 threads.
// ---------------------------------------------------------------------------
__global__ void __launch_bounds__(NTHREADS, 1)
qp_solver_kernel(const float* __restrict__ mu_g, float* __restrict__ out) {
    extern __shared__ float dsm[];
    float* accAll   = dsm + ACC_OFF;
    float* stageAll = dsm + STAGE_OFF;
    float* sy       = dsm + SY_OFF;
    float* sv       = dsm + SV_OFF;
    float* sw       = dsm + SW_OFF;
    __shared__ float red[NWARPS];
    __shared__ int   sched[NWARPS * 10];
    __shared__ int   sflag;

    const int b    = blockIdx.x;
    const int tid  = threadIdx.x;
    const int lane = tid & 31;
    const int wid  = tid >> 5;
    const float* P = g_pack + (size_t)b * INST_STRIDE;
    const float invN = 1.0f / (float)NDIM;

    // ---- balanced static schedule ----
    // warps 0-7: 8 off-diag; warps 8-15: 7 off-diag + 2 diag. Weight ~equal.
    if (tid < 144) {
        const int w = tid / 9, m = tid % 9;
        int e = -1;
        int o = -1, dg = -1;
        if (w < 8) { if (m < 8) o = w * 8 + m; }
        else { if (m < 7) o = 64 + (w - 8) * 7 + m; else dg = (w - 8) * 2 + (m - 7); }
        if (o >= 0) {                          // off-diag linear -> (I,J), I<J
            int I = 0, rem = o;
            while (rem >= 15 - I) { rem -= 15 - I; ++I; }
            const int J = I + 1 + rem;
            const int t = 16 * I - (I * (I - 1)) / 2 + (J - I);
            e = (t << 8) | (I << 4) | J;
        } else if (dg >= 0) {                  // diag tile
            const int t = 16 * dg - (dg * (dg - 1)) / 2;
            e = (t << 8) | (dg << 4) | dg;
        }
        sched[w * 10 + m] = e;
    }
    if (tid >= 144 && tid < 160) sched[(tid - 144) * 10 + 9] = -1;  // guard slot
    if (tid == 0) sflag = 0;
    const float rmu = mu_g[(size_t)b * NDIM + tid];
    sy[tid] = invN;
    __syncthreads();

    // ---- power iteration (answer is step-independent; margin below) ----
    float ry = invN;
    for (int it = 0; it < POWER_ITERS; ++it) {
        const float gi = matvec_sym(P, sy, accAll, stageAll, sched, tid, lane, wid);
        const float ss = block_sum(gi * gi, red, lane, wid);
        const float inv = 1.0f / (sqrtf(ss) + 1e-12f);
        ry = gi * inv;
        sy[tid] = ry;                          // safe: block_sum barriers passed
        __syncthreads();
    }
    const float gi0  = matvec_sym(P, sy, accAll, stageAll, sched, tid, lane, wid);
    const float lmax = block_sum(ry * gi0, red, lane, wid);
    const float step = 1.0f / (2.0f * lmax * 1.08f + 1e-8f);  // 8% margin

    // ---- FISTA with adaptive restart; scalar phase on warp 0 ----
    sy[tid] = invN;
    sw[tid] = invN;
    __syncthreads();
    float t_mom = 1.0f;                        // meaningful in warp 0 only

    for (int it = 0; it < N_ITERS; ++it) {
        const float gi = matvec_sym(P, sy, accAll, stageAll, sched, tid, lane, wid);
        sv[tid] = sy[tid] - step * (2.0f * gi - rmu);
        // warm L1 for the next matvec's first two tiles (overlaps scalar phase)
        prefetch_tile(P, sched[wid * 10] >> 8, lane);
        prefetch_tile(P, sched[wid * 10 + 1] >> 8, lane);
        __syncthreads();                       // (B) sv ready

        if (wid == 0) {
            float vv[16];
            #pragma unroll
            for (int j = 0; j < 16; ++j) vv[j] = sv[(j << 5) + lane];

            // simplex projection: Michelot fixed point (== sort-based theta)
            float s = 0.f;
            #pragma unroll
            for (int j = 0; j < 16; ++j) s += vv[j];
            s = warp_sum(s);
            float theta = (s - 1.0f) * invN;
            #pragma unroll 1
            for (int pit = 0; pit < 40; ++pit) {
                float sa = 0.f, sc = 0.f;
                #pragma unroll
                for (int j = 0; j < 16; ++j) {
                    if (vv[j] > theta) { sa += vv[j]; sc += 1.0f; }
                }
                sa = warp_sum(sa); sc = warp_sum(sc);
                const float tn = (sa - 1.0f) / sc;
                if (tn == theta) break;        // uniform across warp
                theta = tn;
            }

            // restart test + convergence check
            float mx = 0.f, rdot = 0.f;
            #pragma unroll
            for (int j = 0; j < 16; ++j) {
                const float wo  = sw[(j << 5) + lane];
                const float yo  = sy[(j << 5) + lane];
                const float wnj = fmaxf(vv[j] - theta, 0.0f);
                mx   = fmaxf(mx, fabsf(wnj - wo));
                rdot += (yo - wnj) * (wnj - wo);
            }
            mx = warp_max(mx); rdot = warp_sum(rdot);

            float coef;
            if (rdot > 0.0f) { t_mom = 1.0f; coef = 0.0f; }
            else {
                const float tn = 0.5f * (1.0f + sqrtf(1.0f + 4.0f * t_mom * t_mom));
                coef = (t_mom - 1.0f) / tn;
                t_mom = tn;
            }
            #pragma unroll
            for (int j = 0; j < 16; ++j) {
                const float wo  = sw[(j << 5) + lane];
                const float wnj = fmaxf(vv[j] - theta, 0.0f);
                sw[(j << 5) + lane] = wnj;
                sy[(j << 5) + lane] = wnj + coef * (wnj - wo);
            }
            if (lane == 0) sflag = (mx < 1.5e-6f) ? 1 : 0;
        }
        __syncthreads();                       // (C) sy/sw/sflag ready
        if (sflag) break;                      // uniform
    }

    out[(size_t)b * NDIM + tid] = sw[tid];
}

// ---------------------------------------------------------------------------
extern "C" void kernel_launch(void* const* d_in, const int* in_sizes, int n_in,
                              void* d_out, int out_size) {
    const float* mu    = (const float*)d_in[0];   // [128, 512]
    const float* Sigma = (const float*)d_in[1];   // [128, 512, 512]
    float* out = (float*)d_out;                   // [128, 512]

    cudaFuncSetAttribute(qp_solver_kernel,
                         cudaFuncAttributeMaxDynamicSharedMemorySize, DSM_BYTES);

    dim3 gs(NTILES, BATCH);
    dim3 bs(32, 8);
    pack_kernel<<<gs, bs>>>(Sigma);
    qp_solver_kernel<<<BATCH, NTHREADS, DSM_BYTES>>>(mu, out);
}

// round 11
// speedup vs baseline: 1.5140x; 1.0785x over previous
#include <cuda_runtime.h>
#include <math.h>

#define BATCH 128
#define NDIM 512
#define POWER_ITERS 10
#define N_ITERS 500
#define NTHREADS 512
#define NWARPS 16
#define NTILES 136              // 16*17/2 upper-triangular 32x32 tiles
#define TILE_ELEMS 1024
#define INST_STRIDE (NTILES * TILE_ELEMS)   // 544 KB per instance

// dynamic smem layout (floats)
#define ACC_OFF   0                          // 16 x 512  (32 KB)
#define STAGE_OFF 8192                       // 16 x 1152 (72 KB)
#define RES_OFF   (STAGE_OFF + 16 * 1152)    // 24 x 1152 (108 KB) resident tiles
#define SY_OFF    (RES_OFF + 24 * 1152)
#define SV_OFF    (SY_OFF + NDIM)
#define SW_OFF    (SV_OFF + NDIM)
#define DSM_FLOATS (SW_OFF + NDIM)
#define DSM_BYTES (DSM_FLOATS * 4)           // 223,232 B (< 227 KB cap)

// Packed symmetric Sigma: 128 * 544KB = 68 MB (L2-resident)
__device__ float g_pack[(size_t)BATCH * INST_STRIDE];

// ---------------------------------------------------------------------------
// Kernel 1: symmetrize + pack upper triangle (uniform column layout).
// P[k*128 + c*4 + j] = T[4k+j][c],  T = 0.5(S_IJ + S_JI^T)
// ---------------------------------------------------------------------------
__global__ void pack_kernel(const float* __restrict__ Sigma) {
    __shared__ float sA[32][33];
    __shared__ float sB[32][33];
    const int t = blockIdx.x;
    const int b = blockIdx.y;
    int I = 0, rem = t;
    while (rem >= 16 - I) { rem -= 16 - I; ++I; }
    const int J = I + rem;

    const float* S = Sigma + (size_t)b * NDIM * NDIM;
    float* P = g_pack + (size_t)b * INST_STRIDE + (size_t)t * TILE_ELEMS;
    const int tx = threadIdx.x, ty = threadIdx.y;
    const int tid = ty * 32 + tx;

    #pragma unroll
    for (int r = ty; r < 32; r += 8) {
        sA[r][tx] = S[(size_t)(I * 32 + r) * NDIM + J * 32 + tx]; // S[Ib+r][Jb+c]
        sB[r][tx] = S[(size_t)(J * 32 + r) * NDIM + I * 32 + tx]; // S[Jb+r][Ib+c]
    }
    __syncthreads();

    #pragma unroll
    for (int q = 0; q < 4; ++q) {
        const int addr = tid + (q << 8);
        const int k = addr >> 7;
        const int c = (addr >> 2) & 31;
        const int j = addr & 3;
        const int r = (k << 2) + j;
        P[addr] = 0.5f * (sA[r][c] + sB[c][r]);   // T[r][c]
    }
}

// ---------------------------------------------------------------------------
// reductions
// ---------------------------------------------------------------------------
__device__ __forceinline__ float warp_sum(float v) {
    #pragma unroll
    for (int o = 16; o; o >>= 1) v += __shfl_xor_sync(0xffffffffu, v, o);
    return v;
}
__device__ __forceinline__ float warp_max(float v) {
    #pragma unroll
    for (int o = 16; o; o >>= 1) v = fmaxf(v, __shfl_xor_sync(0xffffffffu, v, o));
    return v;
}
__device__ __forceinline__ float block_sum(float v, volatile float* red,
                                           int lane, int wid) {
    v = warp_sum(v);
    __syncthreads();
    if (lane == 0) red[wid] = v;
    __syncthreads();
    float x = (lane < NWARPS) ? red[lane] : 0.0f;
    return warp_sum(x);
}

// prefetch one 4KB tile into L1: each lane touches one 128B line
__device__ __forceinline__ void prefetch_tile(const float* __restrict__ P,
                                              int t, int lane) {
    const char* p = (const char*)(P + t * TILE_ELEMS) + (lane << 7);
    asm volatile("prefetch.global.L1 [%0];" :: "l"(p));
}

// load a packed tile into a pitch-36 SMEM buffer: buf[r*36 + c] = T[r][c]
__device__ __forceinline__ void load_tile_to_buf(const float* __restrict__ P,
                                                 int t, int lane,
                                                 float* __restrict__ buf) {
    const float4* PT4 = (const float4*)(P + t * TILE_ELEMS);
    #pragma unroll
    for (int k = 0; k < 8; ++k) {
        const float4 e4 = PT4[(k << 5) + lane];
        buf[((k << 2) + 0) * 36 + lane] = e4.x;
        buf[((k << 2) + 1) * 36 + lane] = e4.y;
        buf[((k << 2) + 2) * 36 + lane] = e4.z;
        buf[((k << 2) + 3) * 36 + lane] = e4.w;
    }
}

// ---------------------------------------------------------------------------
// Symmetric matvec, staged two-pass per tile, balanced static schedule.
// Entries 0 (all warps) and 1 (warps 0-7) are SMEM-resident: no LDG/STS.
// sched entry: (tileIdx<<8)|(I<<4)|J, -1 = empty. Returns (Ssym*y)[tid].
// ---------------------------------------------------------------------------
__device__ __forceinline__ float matvec_sym(const float* __restrict__ P,
                                            const float* __restrict__ sy,
                                            float* __restrict__ accAll,
                                            float* __restrict__ stageAll,
                                            const float* __restrict__ resAll,
                                            const int* __restrict__ sched,
                                            int tid, int lane, int wid) {
    float* acc = accAll + (wid << 9);
    {
        const float4 z = make_float4(0.f, 0.f, 0.f, 0.f);
        float4* a4 = (float4*)acc;
        a4[lane] = z; a4[lane + 32] = z; a4[lane + 64] = z; a4[lane + 96] = z;
    }
    float* stg = stageAll + wid * 1152;
    const int* ms = sched + wid * 10;

    #pragma unroll 1
    for (int m = 0; m < 9; ++m) {
        const int e = ms[m];
        if (e < 0) break;                      // only trailing sentinels
        const int en = ms[m + 1];
        const bool next_res = (m == 0) && (wid < 8);
        if (en >= 0 && !next_res) prefetch_tile(P, en >> 8, lane);

        const int I = (e >> 4) & 15, J = e & 15;
        const float4* yI4 = (const float4*)(sy + (I << 5));

        if (I == J) {                          // diag tile (global, col layout)
            const float4* PT4 = (const float4*)(P + (e >> 8) * TILE_ELEMS);
            float a0 = 0.f, a1 = 0.f;
            #pragma unroll
            for (int k = 0; k < 8; ++k) {
                const float4 e4 = PT4[(k << 5) + lane];
                const float4 yb = yI4[k];                 // broadcast
                a0 = fmaf(e4.x, yb.x, a0); a1 = fmaf(e4.y, yb.y, a1);
                a0 = fmaf(e4.z, yb.z, a0); a1 = fmaf(e4.w, yb.w, a1);
            }
            acc[(I << 5) + lane] += a0 + a1;
        } else if ((m == 0) || ((m == 1) && (wid < 8))) {
            // -------- resident off-diag tile: pure LDS, both passes --------
            const float* rs = resAll + ((m == 0) ? wid : 16 + wid) * 1152;
            float a0 = 0.f, a1 = 0.f, a2 = 0.f, a3 = 0.f;
            #pragma unroll
            for (int k = 0; k < 8; ++k) {
                const float4 yb = yI4[k];
                a0 = fmaf(rs[((k << 2) + 0) * 36 + lane], yb.x, a0);
                a1 = fmaf(rs[((k << 2) + 1) * 36 + lane], yb.y, a1);
                a2 = fmaf(rs[((k << 2) + 2) * 36 + lane], yb.z, a2);
                a3 = fmaf(rs[((k << 2) + 3) * 36 + lane], yb.w, a3);
            }
            acc[(J << 5) + lane] += (a0 + a1) + (a2 + a3);
            const float4* yJ4 = (const float4*)(sy + (J << 5));
            float b0 = 0.f, b1 = 0.f;
            #pragma unroll
            for (int mm = 0; mm < 8; ++mm) {
                const float4 s  = *(const float4*)(rs + lane * 36 + (mm << 2));
                const float4 yb = yJ4[mm];
                b0 = fmaf(s.x, yb.x, b0); b1 = fmaf(s.y, yb.y, b1);
                b0 = fmaf(s.z, yb.z, b0); b1 = fmaf(s.w, yb.w, b1);
            }
            acc[(I << 5) + lane] += b0 + b1;
        } else {
            // -------- global off-diag tile: LDG + stage round trip ---------
            const float4* PT4 = (const float4*)(P + (e >> 8) * TILE_ELEMS);
            float a0 = 0.f, a1 = 0.f;
            #pragma unroll
            for (int k = 0; k < 8; ++k) {
                const float4 e4 = PT4[(k << 5) + lane];   // rows 4k..4k+3, col=lane
                const float4 yb = yI4[k];
                a0 = fmaf(e4.x, yb.x, a0); a1 = fmaf(e4.y, yb.y, a1);
                a0 = fmaf(e4.z, yb.z, a0); a1 = fmaf(e4.w, yb.w, a1);
                stg[((k << 2) + 0) * 36 + lane] = e4.x;   // conflict-free
                stg[((k << 2) + 1) * 36 + lane] = e4.y;
                stg[((k << 2) + 2) * 36 + lane] = e4.z;
                stg[((k << 2) + 3) * 36 + lane] = e4.w;
            }
            acc[(J << 5) + lane] += a0 + a1;              // (T^T yI) -> block J
            __syncwarp();
            const float4* yJ4 = (const float4*)(sy + (J << 5));
            float b0 = 0.f, b1 = 0.f;
            #pragma unroll
            for (int mm = 0; mm < 8; ++mm) {
                const float4 s  = *(const float4*)(stg + lane * 36 + (mm << 2));
                const float4 yb = yJ4[mm];
                b0 = fmaf(s.x, yb.x, b0); b1 = fmaf(s.y, yb.y, b1);
                b0 = fmaf(s.z, yb.z, b0); b1 = fmaf(s.w, yb.w, b1);
            }
            acc[(I << 5) + lane] += b0 + b1;              // (T yJ) -> block I
            __syncwarp();
        }
    }
    __syncthreads();
    float s0 = 0.f, s1 = 0.f, s2 = 0.f, s3 = 0.f;
    #pragma unroll
    for (int w = 0; w < 4; ++w) {
        s0 += accAll[((4 * w + 0) << 9) + tid];
        s1 += accAll[((4 * w + 1) << 9) + tid];
        s2 += accAll[((4 * w + 2) << 9) + tid];
        s3 += accAll[((4 * w + 3) << 9) + tid];
    }
    return (s0 + s1) + (s2 + s3);
}

// ---------------------------------------------------------------------------
// Kernel 2: per-instance solver. grid=128 CTAs, block=512 threads.
// ---------------------------------------------------------------------------
__global__ void __launch_bounds__(NTHREADS, 1)
qp_solver_kernel(const float* __restrict__ mu_g, float* __restrict__ out) {
    extern __shared__ float dsm[];
    float* accAll   = dsm + ACC_OFF;
    float* stageAll = dsm + STAGE_OFF;
    float* resAll   = dsm + RES_OFF;
    float* sy       = dsm + SY_OFF;
    float* sv       = dsm + SV_OFF;
    float* sw       = dsm + SW_OFF;
    __shared__ float red[NWARPS];
    __shared__ int   sched[NWARPS * 10];
    __shared__ int   sflag;

    const int b    = blockIdx.x;
    const int tid  = threadIdx.x;
    const int lane = tid & 31;
    const int wid  = tid >> 5;
    const float* P = g_pack + (size_t)b * INST_STRIDE;
    const float invN = 1.0f / (float)NDIM;

    // ---- balanced static schedule ----
    // warps 0-7: 8 off-diag; warps 8-15: 7 off-diag + 2 diag.
    if (tid < 144) {
        const int w = tid / 9, m = tid % 9;
        int e = -1;
        int o = -1, dg = -1;
        if (w < 8) { if (m < 8) o = w * 8 + m; }
        else { if (m < 7) o = 64 + (w - 8) * 7 + m; else dg = (w - 8) * 2 + (m - 7); }
        if (o >= 0) {                          // off-diag linear -> (I,J), I<J
            int I = 0, rem = o;
            while (rem >= 15 - I) { rem -= 15 - I; ++I; }
            const int J = I + 1 + rem;
            const int t = 16 * I - (I * (I - 1)) / 2 + (J - I);
            e = (t << 8) | (I << 4) | J;
        } else if (dg >= 0) {                  // diag tile
            const int t = 16 * dg - (dg * (dg - 1)) / 2;
            e = (t << 8) | (dg << 4) | dg;
        }
        sched[w * 10 + m] = e;
    }
    if (tid >= 144 && tid < 160) sched[(tid - 144) * 10 + 9] = -1;  // guard slot
    if (tid == 0) sflag = 0;
    const float rmu = mu_g[(size_t)b * NDIM + tid];
    sy[tid] = invN;
    __syncthreads();

    // ---- preload resident tiles (per-warp private, syncwarp suffices) ----
    load_tile_to_buf(P, sched[wid * 10] >> 8, lane, resAll + wid * 1152);
    if (wid < 8)
        load_tile_to_buf(P, sched[wid * 10 + 1] >> 8, lane,
                         resAll + (16 + wid) * 1152);
    __syncwarp();

    // ---- power iteration (answer is step-independent; margin below) ----
    float ry = invN;
    for (int it = 0; it < POWER_ITERS; ++it) {
        const float gi = matvec_sym(P, sy, accAll, stageAll, resAll, sched,
                                    tid, lane, wid);
        const float ss = block_sum(gi * gi, red, lane, wid);
        const float inv = 1.0f / (sqrtf(ss) + 1e-12f);
        ry = gi * inv;
        sy[tid] = ry;                          // safe: block_sum barriers passed
        __syncthreads();
    }
    const float gi0  = matvec_sym(P, sy, accAll, stageAll, resAll, sched,
                                  tid, lane, wid);
    const float lmax = block_sum(ry * gi0, red, lane, wid);
    const float step = 1.0f / (2.0f * lmax * 1.08f + 1e-8f);  // 8% margin

    // ---- FISTA with adaptive restart; scalar phase on warp 0 ----
    sy[tid] = invN;
    sw[tid] = invN;
    __syncthreads();
    float t_mom = 1.0f;                        // warp-0 state
    float theta_prev = 0.0f;                   // warm-start for Michelot

    for (int it = 0; it < N_ITERS; ++it) {
        const float gi = matvec_sym(P, sy, accAll, stageAll, resAll, sched,
                                    tid, lane, wid);
        sv[tid] = sy[tid] - step * (2.0f * gi - rmu);
        // warm L1 for the next matvec's first non-resident tiles
        {
            const int pb = (wid < 8) ? 2 : 1;
            prefetch_tile(P, sched[wid * 10 + pb] >> 8, lane);
            prefetch_tile(P, sched[wid * 10 + pb + 1] >> 8, lane);
        }
        __syncthreads();                       // (B) sv ready

        if (wid == 0) {
            float vv[16];
            #pragma unroll
            for (int j = 0; j < 16; ++j) vv[j] = sv[(j << 5) + lane];

            // simplex projection: Michelot fixed point (== sort-based theta).
            // Warm-started: any fixed point of g is the unique theta*, so the
            // start value cannot change the answer, only the pass count.
            float s = 0.f;
            #pragma unroll
            for (int j = 0; j < 16; ++j) s += vv[j];
            s = warp_sum(s);
            const float theta_full = (s - 1.0f) * invN;   // classic start
            float theta = theta_prev;
            #pragma unroll 1
            for (int pit = 0; pit < 16; ++pit) {
                float sa = 0.f, sc = 0.f;
                #pragma unroll
                for (int j = 0; j < 16; ++j) {
                    if (vv[j] > theta) { sa += vv[j]; sc += 1.0f; }
                }
                sa = warp_sum(sa); sc = warp_sum(sc);
                if (sc == 0.0f) { theta = theta_full; continue; }  // guard
                const float tn = (sa - 1.0f) / sc;
                if (tn == theta) break;        // uniform across warp
                theta = tn;
            }
            theta_prev = theta;

            // restart test + convergence check
            float mx = 0.f, rdot = 0.f;
            #pragma unroll
            for (int j = 0; j < 16; ++j) {
                const float wo  = sw[(j << 5) + lane];
                const float yo  = sy[(j << 5) + lane];
                const float wnj = fmaxf(vv[j] - theta, 0.0f);
                mx   = fmaxf(mx, fabsf(wnj - wo));
                rdot += (yo - wnj) * (wnj - wo);
            }
            mx = warp_max(mx); rdot = warp_sum(rdot);

            float coef;
            if (rdot > 0.0f) { t_mom = 1.0f; coef = 0.0f; }
            else {
                const float tn = 0.5f * (1.0f + sqrtf(1.0f + 4.0f * t_mom * t_mom));
                coef = (t_mom - 1.0f) / tn;
                t_mom = tn;
            }
            #pragma unroll
            for (int j = 0; j < 16; ++j) {
                const float wo  = sw[(j << 5) + lane];
                const float wnj = fmaxf(vv[j] - theta, 0.0f);
                sw[(j << 5) + lane] = wnj;
                sy[(j << 5) + lane] = wnj + coef * (wnj - wo);
            }
            if (lane == 0) sflag = (mx < 5e-6f) ? 1 : 0;
        }
        __syncthreads();                       // (C) sy/sw/sflag ready
        if (sflag) break;                      // uniform
    }

    out[(size_t)b * NDIM + tid] = sw[tid];
}

// ---------------------------------------------------------------------------
extern "C" void kernel_launch(void* const* d_in, const int* in_sizes, int n_in,
                              void* d_out, int out_size) {
    const float* mu    = (const float*)d_in[0];   // [128, 512]
    const float* Sigma = (const float*)d_in[1];   // [128, 512, 512]
    float* out = (float*)d_out;                   // [128, 512]

    cudaFuncSetAttribute(qp_solver_kernel,
                         cudaFuncAttributeMaxDynamicSharedMemorySize, DSM_BYTES);

    dim3 gs(NTILES, BATCH);
    dim3 bs(32, 8);
    pack_kernel<<<gs, bs>>>(Sigma);
    qp_solver_kernel<<<BATCH, NTHREADS, DSM_BYTES>>>(mu, out);
}